// round 3
// baseline (speedup 1.0000x reference)
#include <cuda_runtime.h>

#define BATCH  16
#define EPSV   1e-5f

// Global scratch (allocation-free: __device__ arrays)
__device__ float  g_sum[BATCH * 16];
__device__ float  g_ssq[BATCH * 16];
__device__ float4 g_A4[BATCH * 16];   // per (batch, channel-quad) scale
__device__ float4 g_B4[BATCH * 16];   // per (batch, channel-quad) shift
__device__ int    g_start[BATCH + 1]; // segment starts in sorted batch_id

// Setup: zero accumulators + binary-search per-batch segment starts.
__global__ void ogn_setup_kernel(const int* __restrict__ batch_id, int nrows) {
    int t = threadIdx.x;              // 256 threads
    g_sum[t] = 0.f;
    g_ssq[t] = 0.f;
    if (t <= BATCH) {
        if (t == BATCH) {
            g_start[t] = nrows;
        } else {
            int lo = 0, hi = nrows;   // first idx with batch_id[idx] >= t
            while (lo < hi) {
                int mid = (lo + hi) >> 1;
                if (__ldg(&batch_id[mid]) < t) lo = mid + 1; else hi = mid;
            }
            g_start[t] = lo;
        }
    }
}

// Pass 1: per-(batch, group) sum and sum-of-squares.
// 256 threads = 16 group-lanes (one float4 = one group's 4 channels)
//             x 16 row-lanes. Contiguous row chunk per block; since batch_id
// is sorted, almost every chunk is single-batch -> branch-free fast path.
__global__ void ogn_pass1_kernel(const float4* __restrict__ data4,
                                 const int* __restrict__ batch_id,
                                 int nrows) {
    __shared__ float s_sum[BATCH][16];
    __shared__ float s_ssq[BATCH][16];
    const int t  = threadIdx.x;
    const int g  = t & 15;
    const int rl = t >> 4;

    int chunk = (nrows + gridDim.x - 1) / gridDim.x;
    int r0 = blockIdx.x * chunk;
    int r1 = min(r0 + chunk, nrows);
    if (r0 >= r1) return;            // block-uniform

    s_sum[rl][g] = 0.f;
    s_ssq[rl][g] = 0.f;
    __syncthreads();

    const int b0 = __ldg(&batch_id[r0]);
    const int b1 = __ldg(&batch_id[r1 - 1]);

    float gsum = 0.f, gssq = 0.f;
    if (b0 == b1) {
        // Fast path: pure stream, loads batch freely across iterations.
        #pragma unroll 4
        for (int row = r0 + rl; row < r1; row += 16) {
            float4 v = __ldg(&data4[(long)row * 16 + g]);
            gsum += (v.x + v.y) + (v.z + v.w);
            gssq += v.x * v.x + v.y * v.y + v.z * v.z + v.w * v.w;
        }
        atomicAdd(&s_sum[b0][g], gsum);
        atomicAdd(&s_ssq[b0][g], gssq);
    } else {
        // Slow path: chunk crosses a batch boundary (rare).
        int cur = -1;
        for (int row = r0 + rl; row < r1; row += 16) {
            int b = __ldg(&batch_id[row]);
            if (b != cur) {
                if (cur >= 0) {
                    atomicAdd(&s_sum[cur][g], gsum);
                    atomicAdd(&s_ssq[cur][g], gssq);
                }
                cur = b; gsum = 0.f; gssq = 0.f;
            }
            float4 v = __ldg(&data4[(long)row * 16 + g]);
            gsum += (v.x + v.y) + (v.z + v.w);
            gssq += v.x * v.x + v.y * v.y + v.z * v.z + v.w * v.w;
        }
        if (cur >= 0) {
            atomicAdd(&s_sum[cur][g], gsum);
            atomicAdd(&s_ssq[cur][g], gssq);
        }
    }
    __syncthreads();

    {
        float s = s_sum[t >> 4][t & 15];
        float q = s_ssq[t >> 4][t & 15];
        if (s != 0.f || q != 0.f) {   // only batches this block touched
            atomicAdd(&g_sum[t], s);
            atomicAdd(&g_ssq[t], q);
        }
    }
}

// Stats: fold mean/inv_std/weights/bias into per-(batch,channel) affine A, B.
__global__ void ogn_stats_kernel(const float* __restrict__ weights,
                                 const float* __restrict__ bias) {
    __shared__ float s_mean[BATCH][16];
    __shared__ float s_istd[BATCH][16];
    int t = threadIdx.x;              // 1024 threads

    if (t < BATCH * 16) {
        int b = t >> 4;
        float n = (float)(g_start[b + 1] - g_start[b]);
        float inv_count = 1.f / (n * 4.f + EPSV);
        float s = g_sum[t], q = g_ssq[t];
        float m = s * inv_count;
        float var = (q - 2.f * m * s + 4.f * n * m * m) * inv_count;
        s_mean[b][t & 15] = m;
        s_istd[b][t & 15] = rsqrtf(var + EPSV);
    }
    __syncthreads();

    {   // 1024 = 16 batches x 64 channels
        int b = t >> 6, c = t & 63, gg = c >> 2;
        float w  = weights[c];
        float bi = bias[c];
        float A  = s_istd[b][gg] * w;
        ((float*)g_A4)[t] = A;
        ((float*)g_B4)[t] = bi - s_mean[b][gg] * A;
    }
}

// Pass 2: out = x * A[b][c] + B[b][c].
// Same chunked layout as pass1: quad-lane g is constant per thread, so in the
// single-batch fast path A/B live in registers and the loop is pure
// LDG.128 / FFMA x4 / STG.128.
__global__ void ogn_pass2_kernel(const float4* __restrict__ data4,
                                 const int* __restrict__ batch_id,
                                 float4* __restrict__ out4,
                                 int nrows) {
    __shared__ float4 sA[BATCH][16];
    __shared__ float4 sB[BATCH][16];
    const int t  = threadIdx.x;
    const int g  = t & 15;
    const int rl = t >> 4;

    int chunk = (nrows + gridDim.x - 1) / gridDim.x;
    int r0 = blockIdx.x * chunk;
    int r1 = min(r0 + chunk, nrows);
    if (r0 >= r1) return;            // block-uniform

    const int b0 = __ldg(&batch_id[r0]);
    const int b1 = __ldg(&batch_id[r1 - 1]);

    if (b0 == b1) {
        float4 a  = __ldg(&g_A4[b0 * 16 + g]);
        float4 bb = __ldg(&g_B4[b0 * 16 + g]);
        #pragma unroll 4
        for (int row = r0 + rl; row < r1; row += 16) {
            long idx = (long)row * 16 + g;
            float4 v = __ldg(&data4[idx]);
            float4 o;
            o.x = fmaf(v.x, a.x, bb.x);
            o.y = fmaf(v.y, a.y, bb.y);
            o.z = fmaf(v.z, a.z, bb.z);
            o.w = fmaf(v.w, a.w, bb.w);
            out4[idx] = o;
        }
    } else {
        if (t < BATCH * 16) { sA[t >> 4][t & 15] = g_A4[t]; sB[t >> 4][t & 15] = g_B4[t]; }
        __syncthreads();
        for (int row = r0 + rl; row < r1; row += 16) {
            long idx = (long)row * 16 + g;
            int b = __ldg(&batch_id[row]);
            float4 v  = __ldg(&data4[idx]);
            float4 a  = sA[b][g];
            float4 bb = sB[b][g];
            float4 o;
            o.x = fmaf(v.x, a.x, bb.x);
            o.y = fmaf(v.y, a.y, bb.y);
            o.z = fmaf(v.z, a.z, bb.z);
            o.w = fmaf(v.w, a.w, bb.w);
            out4[idx] = o;
        }
    }
}

extern "C" void kernel_launch(void* const* d_in, const int* in_sizes, int n_in,
                              void* d_out, int out_size) {
    const float* data     = (const float*)d_in[0];
    const int*   batch_id = (const int*)d_in[1];
    const float* weights  = (const float*)d_in[2];
    const float* bias     = (const float*)d_in[3];
    float*       out      = (float*)d_out;
    const int    nrows    = in_sizes[1];          // batch_id element count = N

    ogn_setup_kernel<<<1, 256>>>(batch_id, nrows);
    ogn_pass1_kernel<<<2048, 256>>>((const float4*)data, batch_id, nrows);
    ogn_stats_kernel<<<1, 1024>>>(weights, bias);
    ogn_pass2_kernel<<<2048, 256>>>((const float4*)data, batch_id,
                                    (float4*)out, nrows);
}

// round 4
// speedup vs baseline: 1.1369x; 1.1369x over previous
#include <cuda_runtime.h>

#define BATCH   16
#define EPSV    1e-5f
#define SLICES  128              // blocks per batch segment
#define TPB     256

// Global scratch (allocation-free: __device__ arrays)
__device__ float  g_sum[BATCH * 16];
__device__ float  g_ssq[BATCH * 16];
__device__ float4 g_A4[BATCH * 16];   // per (batch, channel-quad) scale
__device__ float4 g_B4[BATCH * 16];   // per (batch, channel-quad) shift
__device__ int    g_start[BATCH + 1]; // segment starts in sorted batch_id

// Setup: zero accumulators + binary-search per-batch segment starts.
__global__ void ogn_setup_kernel(const int* __restrict__ batch_id, int nrows) {
    int t = threadIdx.x;              // 256 threads
    g_sum[t] = 0.f;
    g_ssq[t] = 0.f;
    if (t <= BATCH) {
        if (t == BATCH) {
            g_start[t] = nrows;
        } else {
            int lo = 0, hi = nrows;   // first idx with batch_id[idx] >= t
            while (lo < hi) {
                int mid = (lo + hi) >> 1;
                if (__ldg(&batch_id[mid]) < t) lo = mid + 1; else hi = mid;
            }
            g_start[t] = lo;
        }
    }
}

// Pass 1: per-(batch, group) sum / sum-of-squares.
// Segment-aligned strided dispatch: block (b, slice) strides through batch
// b's quad range with stride SLICES*TPB, so the 128 blocks of a batch sweep
// the segment near-sequentially. g-lane (t & 15) is invariant across
// iterations, so accumulation is pure registers; no batch_id, no branches.
__global__ void ogn_pass1_kernel(const float4* __restrict__ data4) {
    const int t     = threadIdx.x;
    const int g     = t & 15;
    const int b     = blockIdx.x & (BATCH - 1);
    const int slice = blockIdx.x >> 4;

    const int q0  = g_start[b] * 16;       // quad-index range of this segment
    const int q1  = g_start[b + 1] * 16;
    const int base = q0 + slice * TPB + t; // base % 16 == t & 15 (q0, slice*TPB mult of 16)

    float gsum = 0.f, gssq = 0.f;
    #pragma unroll 4
    for (int qi = base; qi < q1; qi += SLICES * TPB) {
        float4 v = __ldg(&data4[qi]);
        gsum += (v.x + v.y) + (v.z + v.w);
        gssq += v.x * v.x + v.y * v.y + v.z * v.z + v.w * v.w;
    }

    // lanes t and t+16 in each warp share g: fold, then cross-warp via shared.
    gsum += __shfl_xor_sync(0xffffffffu, gsum, 16);
    gssq += __shfl_xor_sync(0xffffffffu, gssq, 16);

    __shared__ float s_sum[8][16];
    __shared__ float s_ssq[8][16];
    const int w = t >> 5;
    if ((t & 31) < 16) { s_sum[w][g] = gsum; s_ssq[w][g] = gssq; }
    __syncthreads();

    if (t < 16) {
        float s = 0.f, q = 0.f;
        #pragma unroll
        for (int i = 0; i < 8; i++) { s += s_sum[i][t]; q += s_ssq[i][t]; }
        if (s != 0.f || q != 0.f) {
            atomicAdd(&g_sum[b * 16 + t], s);
            atomicAdd(&g_ssq[b * 16 + t], q);
        }
    }
}

// Stats: fold mean/inv_std/weights/bias into per-(batch,channel) affine A, B.
__global__ void ogn_stats_kernel(const float* __restrict__ weights,
                                 const float* __restrict__ bias) {
    __shared__ float s_mean[BATCH][16];
    __shared__ float s_istd[BATCH][16];
    int t = threadIdx.x;              // 1024 threads

    if (t < BATCH * 16) {
        int b = t >> 4;
        float n = (float)(g_start[b + 1] - g_start[b]);
        float inv_count = 1.f / (n * 4.f + EPSV);
        float s = g_sum[t], q = g_ssq[t];
        float m = s * inv_count;
        float var = (q - 2.f * m * s + 4.f * n * m * m) * inv_count;
        s_mean[b][t & 15] = m;
        s_istd[b][t & 15] = rsqrtf(var + EPSV);
    }
    __syncthreads();

    {   // 1024 = 16 batches x 64 channels
        int b = t >> 6, c = t & 63, gg = c >> 2;
        float w  = weights[c];
        float bi = bias[c];
        float A  = s_istd[b][gg] * w;
        ((float*)g_A4)[t] = A;
        ((float*)g_B4)[t] = bi - s_mean[b][gg] * A;
    }
}

// Pass 2: out = x * A[b][c] + B[b][c].
// Same segment-aligned strided dispatch: A/B hoisted into registers, inner
// loop is exactly LDG.128 / 4xFFMA / STG.128.
__global__ void ogn_pass2_kernel(const float4* __restrict__ data4,
                                 float4* __restrict__ out4) {
    const int t     = threadIdx.x;
    const int g     = t & 15;
    const int b     = blockIdx.x & (BATCH - 1);
    const int slice = blockIdx.x >> 4;

    const int q0  = g_start[b] * 16;
    const int q1  = g_start[b + 1] * 16;
    const int base = q0 + slice * TPB + t;

    const float4 a  = __ldg(&g_A4[b * 16 + g]);
    const float4 bb = __ldg(&g_B4[b * 16 + g]);

    #pragma unroll 4
    for (int qi = base; qi < q1; qi += SLICES * TPB) {
        float4 v = __ldg(&data4[qi]);
        float4 o;
        o.x = fmaf(v.x, a.x, bb.x);
        o.y = fmaf(v.y, a.y, bb.y);
        o.z = fmaf(v.z, a.z, bb.z);
        o.w = fmaf(v.w, a.w, bb.w);
        out4[qi] = o;
    }
}

extern "C" void kernel_launch(void* const* d_in, const int* in_sizes, int n_in,
                              void* d_out, int out_size) {
    const float* data     = (const float*)d_in[0];
    const int*   batch_id = (const int*)d_in[1];
    const float* weights  = (const float*)d_in[2];
    const float* bias     = (const float*)d_in[3];
    float*       out      = (float*)d_out;
    const int    nrows    = in_sizes[1];          // batch_id element count = N

    ogn_setup_kernel<<<1, 256>>>(batch_id, nrows);
    ogn_pass1_kernel<<<BATCH * SLICES, TPB>>>((const float4*)data);
    ogn_stats_kernel<<<1, 1024>>>(weights, bias);
    ogn_pass2_kernel<<<BATCH * SLICES, TPB>>>((const float4*)data, (float4*)out);
}

// round 6
// speedup vs baseline: 1.2025x; 1.0578x over previous
#include <cuda_runtime.h>

#define BATCH   16
#define EPSV    1e-5f
#define SLICES  128              // blocks per batch segment
#define TPB     256
#define STRIDE  (SLICES * TPB)   // quad stride per segment sweep

// Global scratch (allocation-free: __device__ arrays)
__device__ float g_sum[BATCH * 16];
__device__ float g_ssq[BATCH * 16];
__device__ int   g_start[BATCH + 1]; // segment starts in sorted batch_id

// Setup: zero accumulators + binary-search per-batch segment starts.
__global__ void ogn_setup_kernel(const int* __restrict__ batch_id, int nrows) {
    int t = threadIdx.x;              // 256 threads
    if (t < BATCH * 16) {
        g_sum[t] = 0.f;
        g_ssq[t] = 0.f;
    }
    if (t <= BATCH) {
        if (t == BATCH) {
            g_start[t] = nrows;
        } else {
            int lo = 0, hi = nrows;   // first idx with batch_id[idx] >= t
            while (lo < hi) {
                int mid = (lo + hi) >> 1;
                if (__ldg(&batch_id[mid]) < t) lo = mid + 1; else hi = mid;
            }
            g_start[t] = lo;
        }
    }
}

// Pass 1: per-(batch, group) sum / sum-of-squares.
// Segment-aligned strided dispatch, FORWARD sweep (leaves each segment's tail
// hot in L2 for pass2's reverse sweep). Two independent load+FMA chains per
// iteration for MLP; default-cached loads so lines populate L2.
__global__ void __launch_bounds__(TPB)
ogn_pass1_kernel(const float4* __restrict__ data4) {
    const int t     = threadIdx.x;
    const int g     = t & 15;
    const int b     = blockIdx.x & (BATCH - 1);
    const int slice = blockIdx.x >> 4;

    const int q1 = g_start[b + 1] * 16;
    int qi = g_start[b] * 16 + slice * TPB + t;

    float s0 = 0.f, s1 = 0.f, qa = 0.f, qb = 0.f;
    #pragma unroll 4
    for (; qi + STRIDE < q1; qi += 2 * STRIDE) {
        float4 va = data4[qi];
        float4 vb = data4[qi + STRIDE];
        s0 += (va.x + va.y) + (va.z + va.w);
        qa += va.x * va.x + va.y * va.y + va.z * va.z + va.w * va.w;
        s1 += (vb.x + vb.y) + (vb.z + vb.w);
        qb += vb.x * vb.x + vb.y * vb.y + vb.z * vb.z + vb.w * vb.w;
    }
    if (qi < q1) {                      // at most one straggler
        float4 v = data4[qi];
        s0 += (v.x + v.y) + (v.z + v.w);
        qa += v.x * v.x + v.y * v.y + v.z * v.z + v.w * v.w;
    }
    float gsum = s0 + s1;
    float gssq = qa + qb;

    // lanes t and t+16 in each warp share g: fold, then cross-warp via shared.
    gsum += __shfl_xor_sync(0xffffffffu, gsum, 16);
    gssq += __shfl_xor_sync(0xffffffffu, gssq, 16);

    __shared__ float s_sum[8][16];
    __shared__ float s_ssq[8][16];
    const int w = t >> 5;
    if ((t & 31) < 16) { s_sum[w][g] = gsum; s_ssq[w][g] = gssq; }
    __syncthreads();

    if (t < 16) {
        float s = 0.f, q = 0.f;
        #pragma unroll
        for (int i = 0; i < 8; i++) { s += s_sum[i][t]; q += s_ssq[i][t]; }
        if (s != 0.f || q != 0.f) {
            atomicAdd(&g_sum[b * 16 + t], s);
            atomicAdd(&g_ssq[b * 16 + t], q);
        }
    }
}

// Pass 2: out = x * A[b][c] + B[b][c].
// Inline per-block stats (reads 32 hot floats, rsqrt) -> register A/B, then a
// REVERSE sweep of this segment so the lines pass1 just left in L2 are
// consumed first. __ldcs/__stcs keep both streams evict-first so the write
// stream doesn't displace the cached read tail.
__global__ void __launch_bounds__(TPB)
ogn_pass2_kernel(const float4* __restrict__ data4,
                 float4* __restrict__ out4,
                 const float* __restrict__ weights,
                 const float* __restrict__ bias) {
    __shared__ float smean[16], sistd[16];
    const int t     = threadIdx.x;
    const int g     = t & 15;
    const int b     = blockIdx.x & (BATCH - 1);
    const int slice = blockIdx.x >> 4;

    const int r0 = g_start[b];
    const int r1 = g_start[b + 1];

    if (t < 16) {
        float n = (float)(r1 - r0);
        float inv_count = 1.f / (n * 4.f + EPSV);
        float s = g_sum[b * 16 + t], q = g_ssq[b * 16 + t];
        float m = s * inv_count;
        float var = (q - 2.f * m * s + 4.f * n * m * m) * inv_count;
        smean[t] = m;
        sistd[t] = rsqrtf(var + EPSV);
    }
    __syncthreads();

    const float4 w4  = __ldg(&((const float4*)weights)[g]);
    const float4 bi4 = __ldg(&((const float4*)bias)[g]);
    const float istd = sistd[g];
    const float m    = smean[g];
    float4 a, bb;
    a.x = istd * w4.x;  a.y = istd * w4.y;  a.z = istd * w4.z;  a.w = istd * w4.w;
    bb.x = bi4.x - m * a.x;  bb.y = bi4.y - m * a.y;
    bb.z = bi4.z - m * a.z;  bb.w = bi4.w - m * a.w;

    const int base = r0 * 16 + slice * TPB + t;
    const int span = r1 * 16 - base;
    if (span > 0) {
        const int kmax = (span + STRIDE - 1) / STRIDE;   // STRIDE is pow2 -> shift
        #pragma unroll 4
        for (int k = kmax - 1; k >= 0; --k) {
            const int qi = base + k * STRIDE;
            float4 v = __ldcs(&data4[qi]);
            float4 o;
            o.x = fmaf(v.x, a.x, bb.x);
            o.y = fmaf(v.y, a.y, bb.y);
            o.z = fmaf(v.z, a.z, bb.z);
            o.w = fmaf(v.w, a.w, bb.w);
            __stcs(&out4[qi], o);
        }
    }
}

extern "C" void kernel_launch(void* const* d_in, const int* in_sizes, int n_in,
                              void* d_out, int out_size) {
    const float* data     = (const float*)d_in[0];
    const int*   batch_id = (const int*)d_in[1];
    const float* weights  = (const float*)d_in[2];
    const float* bias     = (const float*)d_in[3];
    float*       out      = (float*)d_out;
    const int    nrows    = in_sizes[1];          // batch_id element count = N

    ogn_setup_kernel<<<1, 256>>>(batch_id, nrows);
    ogn_pass1_kernel<<<BATCH * SLICES, TPB>>>((const float4*)data);
    ogn_pass2_kernel<<<BATCH * SLICES, TPB>>>((const float4*)data, (float4*)out,
                                              weights, bias);
}

// round 8
// speedup vs baseline: 1.2042x; 1.0013x over previous
#include <cuda_runtime.h>

#define BATCH   16
#define EPSV    1e-5f
#define SLICES  128              // blocks per batch segment
#define TPB     256
#define STRIDE  (SLICES * TPB)   // quad stride per segment sweep

// Global scratch (allocation-free: __device__ arrays)
__device__ float g_sum[BATCH * 16];
__device__ float g_ssq[BATCH * 16];
__device__ int   g_start[BATCH + 1]; // segment starts in sorted batch_id

// Setup: zero accumulators + PARALLEL boundary detection on the sorted
// batch_id (replaces the serial binary search: 16 searches x ~20 dependent
// DRAM loads cost 13.8us; a grid-wide adjacent-pair scan costs ~1-2us).
__global__ void ogn_setup_kernel(const int* __restrict__ batch_id, int nrows) {
    const int t   = threadIdx.x;
    const int idx = blockIdx.x * blockDim.x + t;

    if (blockIdx.x == 0) {
        g_sum[t] = 0.f;                      // TPB == 256 == BATCH*16
        g_ssq[t] = 0.f;
        if (t == 0) {
            g_start[0] = 0;
            int bfirst = __ldg(&batch_id[0]);
            for (int v = 1; v <= bfirst; v++) g_start[v] = 0;          // leading empties
            int blast = __ldg(&batch_id[nrows - 1]);
            for (int v = blast + 1; v <= BATCH; v++) g_start[v] = nrows; // trailing empties
        }
    }

    const int gs = gridDim.x * blockDim.x;
    for (int i = idx; i < nrows - 1; i += gs) {
        int a = __ldg(&batch_id[i]);
        int b = __ldg(&batch_id[i + 1]);
        if (a != b) {
            for (int v = a + 1; v <= b; v++) g_start[v] = i + 1;  // handles skipped batches
        }
    }
}

// Pass 1: per-(batch, group) sum / sum-of-squares.
// Segment-aligned strided dispatch, FORWARD sweep (leaves each segment's tail
// hot in L2 for pass2's reverse sweep). Two independent load+FMA chains per
// iteration for MLP; default-cached loads so lines populate L2.
__global__ void __launch_bounds__(TPB)
ogn_pass1_kernel(const float4* __restrict__ data4) {
    const int t     = threadIdx.x;
    const int g     = t & 15;
    const int b     = blockIdx.x & (BATCH - 1);
    const int slice = blockIdx.x >> 4;

    const int q1 = g_start[b + 1] * 16;
    int qi = g_start[b] * 16 + slice * TPB + t;

    float s0 = 0.f, s1 = 0.f, qa = 0.f, qb = 0.f;
    #pragma unroll 4
    for (; qi + STRIDE < q1; qi += 2 * STRIDE) {
        float4 va = data4[qi];
        float4 vb = data4[qi + STRIDE];
        s0 += (va.x + va.y) + (va.z + va.w);
        qa += va.x * va.x + va.y * va.y + va.z * va.z + va.w * va.w;
        s1 += (vb.x + vb.y) + (vb.z + vb.w);
        qb += vb.x * vb.x + vb.y * vb.y + vb.z * vb.z + vb.w * vb.w;
    }
    if (qi < q1) {                      // at most one straggler
        float4 v = data4[qi];
        s0 += (v.x + v.y) + (v.z + v.w);
        qa += v.x * v.x + v.y * v.y + v.z * v.z + v.w * v.w;
    }
    float gsum = s0 + s1;
    float gssq = qa + qb;

    // lanes t and t+16 in each warp share g: fold, then cross-warp via shared.
    gsum += __shfl_xor_sync(0xffffffffu, gsum, 16);
    gssq += __shfl_xor_sync(0xffffffffu, gssq, 16);

    __shared__ float s_sum[8][16];
    __shared__ float s_ssq[8][16];
    const int w = t >> 5;
    if ((t & 31) < 16) { s_sum[w][g] = gsum; s_ssq[w][g] = gssq; }
    __syncthreads();

    if (t < 16) {
        float s = 0.f, q = 0.f;
        #pragma unroll
        for (int i = 0; i < 8; i++) { s += s_sum[i][t]; q += s_ssq[i][t]; }
        if (s != 0.f || q != 0.f) {
            atomicAdd(&g_sum[b * 16 + t], s);
            atomicAdd(&g_ssq[b * 16 + t], q);
        }
    }
}

// Pass 2: out = x * A[b][c] + B[b][c].
// Inline per-block stats (reads 32 hot floats, rsqrt) -> register A/B, then a
// REVERSE sweep of this segment so the lines pass1 just left in L2 are
// consumed first. __ldcs/__stcs keep both streams evict-first so the write
// stream doesn't displace the cached read tail.
__global__ void __launch_bounds__(TPB)
ogn_pass2_kernel(const float4* __restrict__ data4,
                 float4* __restrict__ out4,
                 const float* __restrict__ weights,
                 const float* __restrict__ bias) {
    __shared__ float smean[16], sistd[16];
    const int t     = threadIdx.x;
    const int g     = t & 15;
    const int b     = blockIdx.x & (BATCH - 1);
    const int slice = blockIdx.x >> 4;

    const int r0 = g_start[b];
    const int r1 = g_start[b + 1];

    if (t < 16) {
        float n = (float)(r1 - r0);
        float inv_count = 1.f / (n * 4.f + EPSV);
        float s = g_sum[b * 16 + t], q = g_ssq[b * 16 + t];
        float m = s * inv_count;
        float var = (q - 2.f * m * s + 4.f * n * m * m) * inv_count;
        smean[t] = m;
        sistd[t] = rsqrtf(var + EPSV);
    }
    __syncthreads();

    const float4 w4  = __ldg(&((const float4*)weights)[g]);
    const float4 bi4 = __ldg(&((const float4*)bias)[g]);
    const float istd = sistd[g];
    const float m    = smean[g];
    float4 a, bb;
    a.x = istd * w4.x;  a.y = istd * w4.y;  a.z = istd * w4.z;  a.w = istd * w4.w;
    bb.x = bi4.x - m * a.x;  bb.y = bi4.y - m * a.y;
    bb.z = bi4.z - m * a.z;  bb.w = bi4.w - m * a.w;

    const int base = r0 * 16 + slice * TPB + t;
    const int span = r1 * 16 - base;
    if (span > 0) {
        const int kmax = (span + STRIDE - 1) / STRIDE;   // STRIDE is pow2 -> shift
        #pragma unroll 4
        for (int k = kmax - 1; k >= 0; --k) {
            const int qi = base + k * STRIDE;
            float4 v = __ldcs(&data4[qi]);
            float4 o;
            o.x = fmaf(v.x, a.x, bb.x);
            o.y = fmaf(v.y, a.y, bb.y);
            o.z = fmaf(v.z, a.z, bb.z);
            o.w = fmaf(v.w, a.w, bb.w);
            __stcs(&out4[qi], o);
        }
    }
}

extern "C" void kernel_launch(void* const* d_in, const int* in_sizes, int n_in,
                              void* d_out, int out_size) {
    const float* data     = (const float*)d_in[0];
    const int*   batch_id = (const int*)d_in[1];
    const float* weights  = (const float*)d_in[2];
    const float* bias     = (const float*)d_in[3];
    float*       out      = (float*)d_out;
    const int    nrows    = in_sizes[1];          // batch_id element count = N

    ogn_setup_kernel<<<264, TPB>>>(batch_id, nrows);
    ogn_pass1_kernel<<<BATCH * SLICES, TPB>>>((const float4*)data);
    ogn_pass2_kernel<<<BATCH * SLICES, TPB>>>((const float4*)data, (float4*)out,
                                              weights, bias);
}

// round 9
// speedup vs baseline: 1.2694x; 1.0542x over previous
#include <cuda_runtime.h>

#define BATCH   16
#define EPSV    1e-5f
#define SLICES  128              // blocks per batch segment
#define TPB     256
#define STRIDE  (SLICES * TPB)   // quad stride per segment sweep

// Global scratch (allocation-free: __device__ arrays)
__device__ float g_sum[BATCH * 16];
__device__ float g_ssq[BATCH * 16];
__device__ int   g_start[BATCH + 1]; // segment starts in sorted batch_id

// Setup: zero accumulators + boundary detection on the sorted batch_id.
// Loop-free per thread: one int4 load (4 ids) + one scalar edge load, all
// independent -> no loop-carried scoreboard drain (the prior versions
// serialized ~15 dependent-load iterations behind a branch = 13us).
__global__ void ogn_setup_kernel(const int* __restrict__ batch_id, int nrows) {
    const int t   = threadIdx.x;
    const int tid = blockIdx.x * blockDim.x + t;

    if (blockIdx.x == 0) {
        g_sum[t] = 0.f;                      // TPB == 256 == BATCH*16
        g_ssq[t] = 0.f;
        if (t == 0) {
            g_start[0] = 0;
            int bfirst = __ldg(&batch_id[0]);
            for (int v = 1; v <= bfirst; v++) g_start[v] = 0;           // leading empties
            int blast = __ldg(&batch_id[nrows - 1]);
            for (int v = blast + 1; v <= BATCH; v++) g_start[v] = nrows; // trailing empties
        }
    }

    const int i0 = tid * 4;                  // this thread's 4-element window
    if (i0 >= nrows - 1) return;

    int e[5];
    if (i0 + 4 < nrows) {                    // fast path: int4 + scalar edge
        int4 v = __ldg(&((const int4*)batch_id)[tid]);
        e[0] = v.x; e[1] = v.y; e[2] = v.z; e[3] = v.w;
        e[4] = __ldg(&batch_id[i0 + 4]);
        #pragma unroll
        for (int j = 0; j < 4; j++) {
            if (e[j] != e[j + 1]) {
                for (int v2 = e[j] + 1; v2 <= e[j + 1]; v2++) g_start[v2] = i0 + j + 1;
            }
        }
    } else {                                 // ragged tail (nrows not mult of 4)
        for (int i = i0; i < nrows - 1; i++) {
            int a = __ldg(&batch_id[i]);
            int b = __ldg(&batch_id[i + 1]);
            if (a != b) {
                for (int v2 = a + 1; v2 <= b; v2++) g_start[v2] = i + 1;
            }
        }
    }
}

// Pass 1: per-(batch, group) sum / sum-of-squares.
// Segment-aligned strided dispatch, FORWARD sweep (leaves each segment's tail
// hot in L2 for pass2's reverse sweep). Two independent load+FMA chains per
// iteration for MLP; default-cached loads so lines populate L2.
__global__ void __launch_bounds__(TPB)
ogn_pass1_kernel(const float4* __restrict__ data4) {
    const int t     = threadIdx.x;
    const int g     = t & 15;
    const int b     = blockIdx.x & (BATCH - 1);
    const int slice = blockIdx.x >> 4;

    const int q1 = g_start[b + 1] * 16;
    int qi = g_start[b] * 16 + slice * TPB + t;

    float s0 = 0.f, s1 = 0.f, qa = 0.f, qb = 0.f;
    #pragma unroll 4
    for (; qi + STRIDE < q1; qi += 2 * STRIDE) {
        float4 va = data4[qi];
        float4 vb = data4[qi + STRIDE];
        s0 += (va.x + va.y) + (va.z + va.w);
        qa += va.x * va.x + va.y * va.y + va.z * va.z + va.w * va.w;
        s1 += (vb.x + vb.y) + (vb.z + vb.w);
        qb += vb.x * vb.x + vb.y * vb.y + vb.z * vb.z + vb.w * vb.w;
    }
    if (qi < q1) {                      // at most one straggler
        float4 v = data4[qi];
        s0 += (v.x + v.y) + (v.z + v.w);
        qa += v.x * v.x + v.y * v.y + v.z * v.z + v.w * v.w;
    }
    float gsum = s0 + s1;
    float gssq = qa + qb;

    // lanes t and t+16 in each warp share g: fold, then cross-warp via shared.
    gsum += __shfl_xor_sync(0xffffffffu, gsum, 16);
    gssq += __shfl_xor_sync(0xffffffffu, gssq, 16);

    __shared__ float s_sum[8][16];
    __shared__ float s_ssq[8][16];
    const int w = t >> 5;
    if ((t & 31) < 16) { s_sum[w][g] = gsum; s_ssq[w][g] = gssq; }
    __syncthreads();

    if (t < 16) {
        float s = 0.f, q = 0.f;
        #pragma unroll
        for (int i = 0; i < 8; i++) { s += s_sum[i][t]; q += s_ssq[i][t]; }
        if (s != 0.f || q != 0.f) {
            atomicAdd(&g_sum[b * 16 + t], s);
            atomicAdd(&g_ssq[b * 16 + t], q);
        }
    }
}

// Pass 2: out = x * A[b][c] + B[b][c].
// Inline per-block stats (reads 32 hot floats, rsqrt) -> register A/B, then a
// REVERSE sweep of this segment so the lines pass1 just left in L2 are
// consumed first. __ldcs/__stcs keep both streams evict-first so the write
// stream doesn't displace the cached read tail.
__global__ void __launch_bounds__(TPB)
ogn_pass2_kernel(const float4* __restrict__ data4,
                 float4* __restrict__ out4,
                 const float* __restrict__ weights,
                 const float* __restrict__ bias) {
    __shared__ float smean[16], sistd[16];
    const int t     = threadIdx.x;
    const int g     = t & 15;
    const int b     = blockIdx.x & (BATCH - 1);
    const int slice = blockIdx.x >> 4;

    const int r0 = g_start[b];
    const int r1 = g_start[b + 1];

    if (t < 16) {
        float n = (float)(r1 - r0);
        float inv_count = 1.f / (n * 4.f + EPSV);
        float s = g_sum[b * 16 + t], q = g_ssq[b * 16 + t];
        float m = s * inv_count;
        float var = (q - 2.f * m * s + 4.f * n * m * m) * inv_count;
        smean[t] = m;
        sistd[t] = rsqrtf(var + EPSV);
    }
    __syncthreads();

    const float4 w4  = __ldg(&((const float4*)weights)[g]);
    const float4 bi4 = __ldg(&((const float4*)bias)[g]);
    const float istd = sistd[g];
    const float m    = smean[g];
    float4 a, bb;
    a.x = istd * w4.x;  a.y = istd * w4.y;  a.z = istd * w4.z;  a.w = istd * w4.w;
    bb.x = bi4.x - m * a.x;  bb.y = bi4.y - m * a.y;
    bb.z = bi4.z - m * a.z;  bb.w = bi4.w - m * a.w;

    const int base = r0 * 16 + slice * TPB + t;
    const int span = r1 * 16 - base;
    if (span > 0) {
        const int kmax = (span + STRIDE - 1) / STRIDE;   // STRIDE is pow2 -> shift
        #pragma unroll 4
        for (int k = kmax - 1; k >= 0; --k) {
            const int qi = base + k * STRIDE;
            float4 v = __ldcs(&data4[qi]);
            float4 o;
            o.x = fmaf(v.x, a.x, bb.x);
            o.y = fmaf(v.y, a.y, bb.y);
            o.z = fmaf(v.z, a.z, bb.z);
            o.w = fmaf(v.w, a.w, bb.w);
            __stcs(&out4[qi], o);
        }
    }
}

extern "C" void kernel_launch(void* const* d_in, const int* in_sizes, int n_in,
                              void* d_out, int out_size) {
    const float* data     = (const float*)d_in[0];
    const int*   batch_id = (const int*)d_in[1];
    const float* weights  = (const float*)d_in[2];
    const float* bias     = (const float*)d_in[3];
    float*       out      = (float*)d_out;
    const int    nrows    = in_sizes[1];          // batch_id element count = N

    const int setup_blocks = (nrows / 4 + TPB - 1) / TPB + 1;  // ~1025 for N=1M
    ogn_setup_kernel<<<setup_blocks, TPB>>>(batch_id, nrows);
    ogn_pass1_kernel<<<BATCH * SLICES, TPB>>>((const float4*)data);
    ogn_pass2_kernel<<<BATCH * SLICES, TPB>>>((const float4*)data, (float4*)out,
                                              weights, bias);
}